// round 15
// baseline (speedup 1.0000x reference)
#include <cuda_runtime.h>
#include <cuda_fp16.h>
#include <stdint.h>

// ---------------------------------------------------------------------------
// EdgeFeat, Round 14: output-column permutation tau on Wcomb (STG.128
// epilogue) + interleaved gamma/beta' pair table (LDS.128). A-side layout
// (paired-k nproj permutation) unchanged from the 125.3us winner.
// tau(n) = ((n>>1)&3)*16 + ((n>>3)&7)*2 + (n&1): frag (nj,tg,b) -> out col
// tg*16 + nj*2 + b  (16 contiguous cols per thread per row).
// ---------------------------------------------------------------------------

#define NODE_DIM 64
#define EDGE_DIM 64
#define GEO_DIM  8
#define GEO_OUT  32
#define COND_DIM 512
#define KTOT     72
#define KPAD     80
#define MAX_NODES  100000
#define MAX_EDGES  800000
#define MAX_GRAPHS 64

#define EDGE_TILE 128
#define WT_STRIDE 88           // halfs
#define GBI_STRIDE 34          // uint2 per graph row (32 data + 2 pad, even)

// edge smem layout (bytes)
#define RAW_BUF_B  (256 * 128)                            // 32768
#define SM_RAW_OFF 0
#define SM_IDX_OFF (2 * RAW_BUF_B)                        // 65536
#define SM_IDX_B   2048
#define SM_W_OFF   (SM_IDX_OFF + 2 * SM_IDX_B)            // 69632
#define SM_W_B     (64 * WT_STRIDE * 2)                   // 11264
#define SM_GB_OFF  (SM_W_OFF + SM_W_B)                    // 80896
#define SM_GB_B    (64 * GBI_STRIDE * 8)                  // 17408
#define SM_TOTAL   (SM_GB_OFF + SM_GB_B)                  // 98304

__device__ __half g_nproj_h[MAX_NODES * NODE_DIM];   // paired-k permuted cols
__device__ float  g_gamma_beta[MAX_GRAPHS * 2 * EDGE_DIM];
__device__ __half g_wcomb_h[KPAD * EDGE_DIM];        // [k][n], natural order
__device__ float  g_cbias[EDGE_DIM];
__device__ int    g_ei_is64;
__device__ int    g_bid_is64;

struct __align__(8) Half4 { __half2 lo, hi; };

__device__ __forceinline__ void cpa16(void* smp, const void* g) {
    unsigned sa = (unsigned)__cvta_generic_to_shared(smp);
    asm volatile("cp.async.cg.shared.global [%0], [%1], 16;" :: "r"(sa), "l"(g) : "memory");
}
#define CP_COMMIT() asm volatile("cp.async.commit_group;" ::: "memory")
#define CP_WAIT0()  asm volatile("cp.async.wait_group 0;" ::: "memory")

#define WCOMB_BLOCKS 20
#define NW_STRIDE 72   // halfs

// ---------------------------------------------------------------------------
// Fused kernel: nproj tiles + FiLM + Wcomb/cbias + dtype detect.
// (unchanged from 125.3us winner)
// ---------------------------------------------------------------------------
__global__ __launch_bounds__(256) void fused_kernel(const float* __restrict__ nf,
                                                    const float* __restrict__ Wn,
                                                    const float* __restrict__ bn,
                                                    const float* __restrict__ cond,
                                                    const float* __restrict__ Wc,
                                                    const float* __restrict__ bc,
                                                    const float* __restrict__ Wg,
                                                    const float* __restrict__ bg,
                                                    const float* __restrict__ Wx,
                                                    const void* __restrict__ ei,
                                                    const void* __restrict__ bids,
                                                    int N, int B, int E, int npb) {
    int bx = blockIdx.x;
    int tid = threadIdx.x;

    if (bx < npb) {
        // ================= nproj tile (fp16 MMA) =================
        __shared__ __align__(16) __half As[128 * 64];
        __shared__ __align__(16) __half Ws[64 * NW_STRIDE];
        int lane = tid & 31;
        int wid = tid >> 5;
        int n0 = bx * 128;

        for (int i = tid; i < 64 * 64; i += 256) {
            int k = i >> 6, n = i & 63;
            Ws[n * NW_STRIDE + k] = __float2half_rn(Wn[k * 64 + n]);
        }
        {
            int row = tid >> 1, h = tid & 1;
            int n = n0 + row;
            #pragma unroll
            for (int j = 0; j < 4; j++) {
                int c = h * 4 + j;
                int base = row * 64 + ((c ^ (row & 7)) * 8);
                if (n < N) {
                    float4 a = *(const float4*)&nf[(size_t)n * 64 + c * 8];
                    float4 b = *(const float4*)&nf[(size_t)n * 64 + c * 8 + 4];
                    Half4 hv, hv2;
                    hv.lo  = __floats2half2_rn(a.x, a.y);
                    hv.hi  = __floats2half2_rn(a.z, a.w);
                    hv2.lo = __floats2half2_rn(b.x, b.y);
                    hv2.hi = __floats2half2_rn(b.z, b.w);
                    *(Half4*)&As[base]     = hv;
                    *(Half4*)&As[base + 4] = hv2;
                } else {
                    Half4 hv;
                    hv.lo = __float2half2_rn(0.f);
                    hv.hi = __float2half2_rn(0.f);
                    *(Half4*)&As[base]     = hv;
                    *(Half4*)&As[base + 4] = hv;
                }
            }
        }
        __syncthreads();

        int gid = lane >> 2;
        int tg = lane & 3;
        float2 bnj[8];
        #pragma unroll
        for (int nj = 0; nj < 8; nj++)
            bnj[nj] = *(const float2*)&bn[nj * 8 + tg * 2];

        float acc[8][4];
        #pragma unroll
        for (int nj = 0; nj < 8; nj++)
            #pragma unroll
            for (int q = 0; q < 4; q++) acc[nj][q] = 0.f;

        const char* rbase = (const char*)As;
        const int roff  = (wid * 16 + gid) * 128 + tg * 4;
        const int roff8 = roff + 8 * 128;

        #pragma unroll
        for (int ks = 0; ks < 4; ks++) {
            int co0 = ((2 * ks) ^ gid) * 16;
            int co1 = ((2 * ks + 1) ^ gid) * 16;
            unsigned a0 = *(const unsigned*)(rbase + roff  + co0);
            unsigned a1 = *(const unsigned*)(rbase + roff8 + co0);
            unsigned a2 = *(const unsigned*)(rbase + roff  + co1);
            unsigned a3 = *(const unsigned*)(rbase + roff8 + co1);
            #pragma unroll
            for (int nj = 0; nj < 8; nj++) {
                const __half* wr = Ws + (nj * 8 + gid) * NW_STRIDE + ks * 16;
                unsigned bb0 = *(const unsigned*)&wr[tg * 2];
                unsigned bb1 = *(const unsigned*)&wr[8 + tg * 2];
                asm volatile(
                    "mma.sync.aligned.m16n8k16.row.col.f32.f16.f16.f32 "
                    "{%0,%1,%2,%3}, {%4,%5,%6,%7}, {%8,%9}, {%0,%1,%2,%3};\n"
                    : "+f"(acc[nj][0]), "+f"(acc[nj][1]),
                      "+f"(acc[nj][2]), "+f"(acc[nj][3])
                    : "r"(a0), "r"(a1), "r"(a2), "r"(a3), "r"(bb0), "r"(bb1));
            }
        }

        // paired-k permuted store
        #pragma unroll
        for (int h = 0; h < 2; h++) {
            int n = n0 + wid * 16 + gid + h * 8;
            if (n < N) {
                __half2 hp[8];
                #pragma unroll
                for (int nj = 0; nj < 8; nj++)
                    hp[nj] = __floats2half2_rn(acc[nj][h * 2] + bnj[nj].x,
                                               acc[nj][h * 2 + 1] + bnj[nj].y);
                #pragma unroll
                for (int q16 = 0; q16 < 4; q16++) {
                    uint2 v;
                    v.x = *(unsigned*)&hp[2 * q16];
                    v.y = *(unsigned*)&hp[2 * q16 + 1];
                    *(uint2*)&g_nproj_h[(size_t)n * 64 + q16 * 16 + tg * 4] = v;
                }
            }
        }
        return;
    }

    int pb = bx - npb;
    if (pb < B) {
        // ================= FiLM, MLP-16 =================
        __shared__ float part[2 * EDGE_DIM];
        int b = pb;
        int j = tid & 127;
        int h = tid >> 7;
        const float* crow = cond + (size_t)b * COND_DIM + h * 256;
        const float* wcol = Wc + (size_t)h * 256 * (2 * EDGE_DIM) + j;
        float accs[16];
        #pragma unroll
        for (int u = 0; u < 16; u++) accs[u] = 0.f;
        for (int k0 = 0; k0 < 256; k0 += 16) {
            #pragma unroll
            for (int u = 0; u < 16; u++)
                accs[u] = fmaf(crow[k0 + u],
                               wcol[(size_t)(k0 + u) * (2 * EDGE_DIM)],
                               accs[u]);
        }
        #pragma unroll
        for (int s = 8; s > 0; s >>= 1)
            #pragma unroll
            for (int u = 0; u < 8; u++)
                if (u < s) accs[u] += accs[u + s];
        float acc = accs[0];
        if (h == 1) part[j] = acc;
        __syncthreads();
        if (h == 0) {
            acc += part[j] + bc[j];
            if (j < EDGE_DIM) acc += 1.0f;
            g_gamma_beta[b * (2 * EDGE_DIM) + j] = acc;
        }
    } else if (pb < B + WCOMB_BLOCKS) {
        int idx = (pb - B) * 256 + tid;
        if (idx < KPAD * EDGE_DIM) {
            int k = idx >> 6, c = idx & 63;
            float v = 0.f;
            if (k < EDGE_DIM) {
                v = Wx[k * EDGE_DIM + c];               // natural order
            } else if (k < KTOT) {
                int gk = k - EDGE_DIM;
                #pragma unroll
                for (int m = 0; m < GEO_OUT; m++)
                    v += Wg[gk * GEO_OUT + m] * Wx[(EDGE_DIM + m) * EDGE_DIM + c];
            }
            g_wcomb_h[idx] = __float2half_rn(v);
        }
        if (pb == B && tid < EDGE_DIM) {
            int c = tid;
            float v = 0.f;
            #pragma unroll
            for (int m = 0; m < GEO_OUT; m++)
                v += bg[m] * Wx[(EDGE_DIM + m) * EDGE_DIM + c];
            g_cbias[c] = v;
        }
    } else {
        // dtype probe: values < 2^17; nonzero high word => int32 packing
        __shared__ int bad[2];
        if (tid == 0) { bad[0] = 0; bad[1] = 0; }
        __syncthreads();
        const unsigned long long* p64 = (const unsigned long long*)ei;
        const unsigned long long* b64 = (const unsigned long long*)bids;
        const int samples = 2048;
        long long st_e = (long long)E / samples; if (st_e < 1) st_e = 1;
        for (int i = tid; i < samples; i += blockDim.x) {
            long long idx = (long long)i * st_e;
            if (idx >= E) break;
            if (p64[idx] >> 32) bad[0] = 1;
        }
        long long n_b = E / 2;
        long long st_b = n_b / samples; if (st_b < 1) st_b = 1;
        for (int i = tid; i < samples; i += blockDim.x) {
            long long idx = (long long)i * st_b;
            if (idx >= n_b) break;
            if (b64[idx] >> 32) bad[1] = 1;
        }
        __syncthreads();
        if (tid == 0) { g_ei_is64 = !bad[0]; g_bid_is64 = !bad[1]; }
    }
}

// ---------------------------------------------------------------------------
// Edge kernel: tau-permuted Wcomb cols -> contiguous per-thread outputs
// (STG.128 x8), interleaved gamma/beta' pairs (LDS.128 x8).
// ---------------------------------------------------------------------------
__global__ __launch_bounds__(256, 2) void edge_kernel(const void* __restrict__ ei,
                                                      const void* __restrict__ bids,
                                                      const float* __restrict__ e_geo,
                                                      float* __restrict__ out,
                                                      int E, int ntiles) {
    extern __shared__ __align__(16) char sm[];
    char*   RAW  = sm + SM_RAW_OFF;
    char*   IDX  = sm + SM_IDX_OFF;
    __half* Wt   = (__half*)(sm + SM_W_OFF);
    uint2*  GBI  = (uint2*)(sm + SM_GB_OFF);

    const int tid = threadIdx.x;
    const int lane = tid & 31;
    const int wid = tid >> 5;
    const int ei64 = g_ei_is64;
    const int bid64 = g_bid_is64;
    const int esz = ei64 ? 8 : 4;

    // Wt[n][k] holds Wcomb col tau(n): frag (nj,tg,b) -> out col tg*16+nj*2+b
    for (int i = tid; i < KTOT * EDGE_DIM; i += 256) {
        int k = i / 64, n = i & 63;
        int tn = ((n >> 1) & 3) * 16 + ((n >> 3) & 7) * 2 + (n & 1);
        Wt[n * WT_STRIDE + k] = g_wcomb_h[k * 64 + tn];
    }
    // GBI[b][p] = {gamma2(2p,2p+1), beta'2(2p,2p+1)}, beta' = beta + cbias*gamma
    for (int i = tid; i < 64 * 32; i += 256) {
        int b = i >> 5, p = i & 31;
        float g0 = g_gamma_beta[b * 128 + 2 * p];
        float g1 = g_gamma_beta[b * 128 + 2 * p + 1];
        float be0 = g_gamma_beta[b * 128 + 64 + 2 * p]     + g_cbias[2 * p] * g0;
        float be1 = g_gamma_beta[b * 128 + 64 + 2 * p + 1] + g_cbias[2 * p + 1] * g1;
        __half2 hg = __floats2half2_rn(g0, g1);
        __half2 hb = __floats2half2_rn(be0, be1);
        uint2 v;
        v.x = *(unsigned*)&hg;
        v.y = *(unsigned*)&hb;
        GBI[b * GBI_STRIDE + p] = v;
    }
    __syncthreads();

    const int gid = lane >> 2;
    const int tg = lane & 3;

    unsigned bfr[8][4];
    unsigned b8[8];
    #pragma unroll
    for (int nj = 0; nj < 8; nj++) {
        const __half* wr = Wt + (nj * 8 + gid) * WT_STRIDE;
        #pragma unroll
        for (int ks = 0; ks < 2; ks++) {
            bfr[nj][ks * 2 + 0] = *(const unsigned*)&wr[ks * 16 + tg * 2];
            bfr[nj][ks * 2 + 1] = *(const unsigned*)&wr[ks * 16 + 8 + tg * 2];
        }
        b8[nj] = *(const unsigned*)&wr[64 + tg * 2];
    }

    const int rowS = wid * 16 + gid;

    auto copy_idx = [&](int tile, int buf) {
        int e0 = tile * EDGE_TILE;
        int nch = 8 * esz;
        int epc = 16 / esz;
        char* dst = IDX + buf * SM_IDX_B;
        if (tid < nch) {
            if (e0 + tid * epc < E)
                cpa16(dst + tid * 16, (const char*)ei + (size_t)e0 * esz + tid * 16);
        } else if (tid >= 128 && tid - 128 < nch) {
            int t = tid - 128;
            if (e0 + t * epc < E)
                cpa16(dst + nch * 16 + t * 16,
                      (const char*)ei + ((size_t)E + e0) * esz + t * 16);
        }
    };
    auto gather_raw = [&](int tile, int rbuf, int ibuf) {
        int e0 = tile * EDGE_TILE;
        char* rb = RAW + rbuf * RAW_BUF_B;
        const char* idxb = IDX + ibuf * SM_IDX_B;
        #pragma unroll
        for (int j = 0; j < 8; j++) {
            int g = j * 256 + tid;
            int row = g >> 3, c = g & 7;
            int e = e0 + (row & 127);
            int idx = 0;
            if (e < E)
                idx = ei64 ? (int)((const long long*)idxb)[row]
                           : ((const int*)idxb)[row];
            cpa16(rb + row * 128 + ((c ^ (row & 7)) * 16),
                  (const char*)g_nproj_h + (size_t)idx * 128 + c * 16);
        }
    };

    int tile = blockIdx.x;
    if (tile >= ntiles) return;
    const int stride = gridDim.x;

    copy_idx(tile, 0);
    CP_COMMIT();
    CP_WAIT0();
    __syncthreads();
    gather_raw(tile, 0, 0);
    { int t1 = tile + stride; if (t1 < ntiles) copy_idx(t1, 1); }
    CP_COMMIT();

    for (int i = 0; tile < ntiles; tile += stride, i++) {
        CP_WAIT0();
        __syncthreads();

        {
            int t1 = tile + stride;
            int t2 = tile + 2 * stride;
            if (t1 < ntiles) gather_raw(t1, (i + 1) & 1, (i + 1) & 1);
            if (t2 < ntiles) copy_idx(t2, i & 1);
            CP_COMMIT();
        }

        const char* rbase = RAW + (i & 1) * RAW_BUF_B;
        int e0 = tile * EDGE_TILE;

        int e1 = e0 + wid * 16 + gid;
        int e2 = e1 + 8;
        float2 gv0 = make_float2(0.f, 0.f), gv1 = make_float2(0.f, 0.f);
        if (e1 < E) gv0 = *(const float2*)&e_geo[(size_t)e1 * GEO_DIM + tg * 2];
        if (e2 < E) gv1 = *(const float2*)&e_geo[(size_t)e2 * GEO_DIM + tg * 2];

        float acc[8][4];
        #pragma unroll
        for (int nj = 0; nj < 8; nj++)
            #pragma unroll
            for (int q = 0; q < 4; q++) acc[nj][q] = 0.f;

        #pragma unroll
        for (int ks = 0; ks < 4; ks++) {
            int q = ks * 4 + tg;
            int off = (((q >> 1) ^ gid) * 16) + ((q & 1) * 8);
            const char* sp = rbase + rowS * 128 + off;
            uint2 s0 = *(const uint2*)(sp);
            uint2 s1 = *(const uint2*)(sp + 8 * 128);
            uint2 d0 = *(const uint2*)(sp + 128 * 128);
            uint2 d1 = *(const uint2*)(sp + 136 * 128);
            __half2 p0 = __hmul2(*(__half2*)&s0.x, *(__half2*)&d0.x);
            __half2 p2 = __hmul2(*(__half2*)&s0.y, *(__half2*)&d0.y);
            __half2 p1 = __hmul2(*(__half2*)&s1.x, *(__half2*)&d1.x);
            __half2 p3 = __hmul2(*(__half2*)&s1.y, *(__half2*)&d1.y);
            unsigned a0 = *(unsigned*)&p0;
            unsigned a1 = *(unsigned*)&p1;
            unsigned a2 = *(unsigned*)&p2;
            unsigned a3 = *(unsigned*)&p3;
            #pragma unroll
            for (int nj = 0; nj < 8; nj++) {
                unsigned bb0, bb1;
                if (ks < 2) {
                    bb0 = bfr[nj][ks * 2];
                    bb1 = bfr[nj][ks * 2 + 1];
                } else {
                    const __half* wr = Wt + (nj * 8 + gid) * WT_STRIDE + ks * 16;
                    bb0 = *(const unsigned*)&wr[tg * 2];
                    bb1 = *(const unsigned*)&wr[8 + tg * 2];
                }
                asm volatile(
                    "mma.sync.aligned.m16n8k16.row.col.f32.f16.f16.f32 "
                    "{%0,%1,%2,%3}, {%4,%5,%6,%7}, {%8,%9}, {%0,%1,%2,%3};\n"
                    : "+f"(acc[nj][0]), "+f"(acc[nj][1]),
                      "+f"(acc[nj][2]), "+f"(acc[nj][3])
                    : "r"(a0), "r"(a1), "r"(a2), "r"(a3),
                      "r"(bb0), "r"(bb1));
            }
        }
        {
            __half2 h0 = __floats2half2_rn(gv0.x, gv0.y);
            __half2 h1 = __floats2half2_rn(gv1.x, gv1.y);
            unsigned ag0 = *(unsigned*)&h0;
            unsigned ag1 = *(unsigned*)&h1;
            #pragma unroll
            for (int nj = 0; nj < 8; nj++) {
                asm volatile(
                    "mma.sync.aligned.m16n8k8.row.col.f32.f16.f16.f32 "
                    "{%0,%1,%2,%3}, {%4,%5}, {%6}, {%0,%1,%2,%3};\n"
                    : "+f"(acc[nj][0]), "+f"(acc[nj][1]),
                      "+f"(acc[nj][2]), "+f"(acc[nj][3])
                    : "r"(ag0), "r"(ag1), "r"(b8[nj]));
            }
        }

        // epilogue: thread covers out cols [tg*16, tg*16+16) per row.
        // gamma/beta' via LDS.128 (pairs nj contiguous), stores via STG.128.
        #pragma unroll
        for (int h = 0; h < 2; h++) {
            int e = e0 + wid * 16 + gid + h * 8;
            if (e < E) {
                int bb = bid64 ? (int)((const long long*)bids)[e]
                               : ((const int*)bids)[e];
                const uint4* gp = (const uint4*)(GBI + bb * GBI_STRIDE + tg * 8);
                float* orow = out + (size_t)e * 64 + tg * 16;
                #pragma unroll
                for (int j = 0; j < 4; j++) {
                    uint4 g4 = gp[j];
                    float2 ga0 = __half22float2(*(__half2*)&g4.x);
                    float2 be0 = __half22float2(*(__half2*)&g4.y);
                    float2 ga1 = __half22float2(*(__half2*)&g4.z);
                    float2 be1 = __half22float2(*(__half2*)&g4.w);
                    float4 o;
                    o.x = fmaxf(fmaf(acc[2 * j][h * 2 + 0],     ga0.x, be0.x), 0.f);
                    o.y = fmaxf(fmaf(acc[2 * j][h * 2 + 1],     ga0.y, be0.y), 0.f);
                    o.z = fmaxf(fmaf(acc[2 * j + 1][h * 2 + 0], ga1.x, be1.x), 0.f);
                    o.w = fmaxf(fmaf(acc[2 * j + 1][h * 2 + 1], ga1.y, be1.y), 0.f);
                    *(float4*)(orow + j * 4) = o;
                }
            }
        }
    }
}

// ---------------------------------------------------------------------------
extern "C" void kernel_launch(void* const* d_in, const int* in_sizes, int n_in,
                              void* d_out, int out_size) {
    const float* nf   = (const float*)d_in[0];
    const void*  ei   = d_in[1];
    const float* eg   = (const float*)d_in[2];
    const float* cond = (const float*)d_in[3];
    const void*  bids = d_in[4];
    const float* Wn   = (const float*)d_in[5];
    const float* bn   = (const float*)d_in[6];
    const float* Wg   = (const float*)d_in[7];
    const float* bg   = (const float*)d_in[8];
    const float* Wc   = (const float*)d_in[9];
    const float* bc   = (const float*)d_in[10];
    const float* Wx   = (const float*)d_in[11];
    float* out = (float*)d_out;

    int N = in_sizes[0] / NODE_DIM;
    int E = in_sizes[2] / GEO_DIM;
    int B = in_sizes[3] / COND_DIM;
    int ntiles = (E + EDGE_TILE - 1) / EDGE_TILE;
    int npb = (N + 127) / 128;

    static int smem_set = 0;
    if (!smem_set) {
        cudaFuncSetAttribute(edge_kernel,
                             cudaFuncAttributeMaxDynamicSharedMemorySize,
                             SM_TOTAL);
        smem_set = 1;
    }

    fused_kernel<<<npb + B + WCOMB_BLOCKS + 1, 256>>>(nf, Wn, bn, cond, Wc, bc,
                                                      Wg, bg, Wx, ei, bids,
                                                      N, B, E, npb);
    int grid = 296;
    if (grid > ntiles) grid = ntiles;
    edge_kernel<<<grid, 256, SM_TOTAL>>>(ei, bids, eg, out, E, ntiles);
}

// round 16
// speedup vs baseline: 1.1416x; 1.1416x over previous
#include <cuda_runtime.h>
#include <cuda_fp16.h>
#include <stdint.h>

// ---------------------------------------------------------------------------
// EdgeFeat, Round 15: revert to Round-12 epilogue (sector-aligned STG.64;
// tau experiment regressed via 2x L2 write amplification) + bids prefetched
// at tile top. A-side paired-k layout, beta' fold unchanged.
// ---------------------------------------------------------------------------

#define NODE_DIM 64
#define EDGE_DIM 64
#define GEO_DIM  8
#define GEO_OUT  32
#define COND_DIM 512
#define KTOT     72
#define KPAD     80
#define MAX_NODES  100000
#define MAX_EDGES  800000
#define MAX_GRAPHS 64

#define EDGE_TILE 128
#define WT_STRIDE 88           // halfs
#define GB_STRIDE 132          // halfs (128 data + 4 pad)

// edge smem layout (bytes)
#define RAW_BUF_B  (256 * 128)                            // 32768
#define SM_RAW_OFF 0
#define SM_IDX_OFF (2 * RAW_BUF_B)                        // 65536
#define SM_IDX_B   2048
#define SM_W_OFF   (SM_IDX_OFF + 2 * SM_IDX_B)            // 69632
#define SM_W_B     (64 * WT_STRIDE * 2)                   // 11264
#define SM_GB_OFF  (SM_W_OFF + SM_W_B)                    // 80896
#define SM_GB_B    (64 * GB_STRIDE * 2)                   // 16896
#define SM_TOTAL   (SM_GB_OFF + SM_GB_B)                  // 97792

__device__ __half g_nproj_h[MAX_NODES * NODE_DIM];   // paired-k permuted cols
__device__ float  g_gamma_beta[MAX_GRAPHS * 2 * EDGE_DIM];
__device__ __half g_wcomb_h[KPAD * EDGE_DIM];        // [k][n], natural order
__device__ float  g_cbias[EDGE_DIM];
__device__ int    g_ei_is64;
__device__ int    g_bid_is64;

struct __align__(8) Half4 { __half2 lo, hi; };

__device__ __forceinline__ void cpa16(void* smp, const void* g) {
    unsigned sa = (unsigned)__cvta_generic_to_shared(smp);
    asm volatile("cp.async.cg.shared.global [%0], [%1], 16;" :: "r"(sa), "l"(g) : "memory");
}
#define CP_COMMIT() asm volatile("cp.async.commit_group;" ::: "memory")
#define CP_WAIT0()  asm volatile("cp.async.wait_group 0;" ::: "memory")

#define WCOMB_BLOCKS 20
#define NW_STRIDE 72   // halfs

// ---------------------------------------------------------------------------
// Fused kernel: nproj tiles + FiLM + Wcomb/cbias + dtype detect.
// (unchanged from 125.3us winner)
// ---------------------------------------------------------------------------
__global__ __launch_bounds__(256) void fused_kernel(const float* __restrict__ nf,
                                                    const float* __restrict__ Wn,
                                                    const float* __restrict__ bn,
                                                    const float* __restrict__ cond,
                                                    const float* __restrict__ Wc,
                                                    const float* __restrict__ bc,
                                                    const float* __restrict__ Wg,
                                                    const float* __restrict__ bg,
                                                    const float* __restrict__ Wx,
                                                    const void* __restrict__ ei,
                                                    const void* __restrict__ bids,
                                                    int N, int B, int E, int npb) {
    int bx = blockIdx.x;
    int tid = threadIdx.x;

    if (bx < npb) {
        // ================= nproj tile (fp16 MMA) =================
        __shared__ __align__(16) __half As[128 * 64];
        __shared__ __align__(16) __half Ws[64 * NW_STRIDE];
        int lane = tid & 31;
        int wid = tid >> 5;
        int n0 = bx * 128;

        for (int i = tid; i < 64 * 64; i += 256) {
            int k = i >> 6, n = i & 63;
            Ws[n * NW_STRIDE + k] = __float2half_rn(Wn[k * 64 + n]);
        }
        {
            int row = tid >> 1, h = tid & 1;
            int n = n0 + row;
            #pragma unroll
            for (int j = 0; j < 4; j++) {
                int c = h * 4 + j;
                int base = row * 64 + ((c ^ (row & 7)) * 8);
                if (n < N) {
                    float4 a = *(const float4*)&nf[(size_t)n * 64 + c * 8];
                    float4 b = *(const float4*)&nf[(size_t)n * 64 + c * 8 + 4];
                    Half4 hv, hv2;
                    hv.lo  = __floats2half2_rn(a.x, a.y);
                    hv.hi  = __floats2half2_rn(a.z, a.w);
                    hv2.lo = __floats2half2_rn(b.x, b.y);
                    hv2.hi = __floats2half2_rn(b.z, b.w);
                    *(Half4*)&As[base]     = hv;
                    *(Half4*)&As[base + 4] = hv2;
                } else {
                    Half4 hv;
                    hv.lo = __float2half2_rn(0.f);
                    hv.hi = __float2half2_rn(0.f);
                    *(Half4*)&As[base]     = hv;
                    *(Half4*)&As[base + 4] = hv;
                }
            }
        }
        __syncthreads();

        int gid = lane >> 2;
        int tg = lane & 3;
        float2 bnj[8];
        #pragma unroll
        for (int nj = 0; nj < 8; nj++)
            bnj[nj] = *(const float2*)&bn[nj * 8 + tg * 2];

        float acc[8][4];
        #pragma unroll
        for (int nj = 0; nj < 8; nj++)
            #pragma unroll
            for (int q = 0; q < 4; q++) acc[nj][q] = 0.f;

        const char* rbase = (const char*)As;
        const int roff  = (wid * 16 + gid) * 128 + tg * 4;
        const int roff8 = roff + 8 * 128;

        #pragma unroll
        for (int ks = 0; ks < 4; ks++) {
            int co0 = ((2 * ks) ^ gid) * 16;
            int co1 = ((2 * ks + 1) ^ gid) * 16;
            unsigned a0 = *(const unsigned*)(rbase + roff  + co0);
            unsigned a1 = *(const unsigned*)(rbase + roff8 + co0);
            unsigned a2 = *(const unsigned*)(rbase + roff  + co1);
            unsigned a3 = *(const unsigned*)(rbase + roff8 + co1);
            #pragma unroll
            for (int nj = 0; nj < 8; nj++) {
                const __half* wr = Ws + (nj * 8 + gid) * NW_STRIDE + ks * 16;
                unsigned bb0 = *(const unsigned*)&wr[tg * 2];
                unsigned bb1 = *(const unsigned*)&wr[8 + tg * 2];
                asm volatile(
                    "mma.sync.aligned.m16n8k16.row.col.f32.f16.f16.f32 "
                    "{%0,%1,%2,%3}, {%4,%5,%6,%7}, {%8,%9}, {%0,%1,%2,%3};\n"
                    : "+f"(acc[nj][0]), "+f"(acc[nj][1]),
                      "+f"(acc[nj][2]), "+f"(acc[nj][3])
                    : "r"(a0), "r"(a1), "r"(a2), "r"(a3), "r"(bb0), "r"(bb1));
            }
        }

        // paired-k permuted store
        #pragma unroll
        for (int h = 0; h < 2; h++) {
            int n = n0 + wid * 16 + gid + h * 8;
            if (n < N) {
                __half2 hp[8];
                #pragma unroll
                for (int nj = 0; nj < 8; nj++)
                    hp[nj] = __floats2half2_rn(acc[nj][h * 2] + bnj[nj].x,
                                               acc[nj][h * 2 + 1] + bnj[nj].y);
                #pragma unroll
                for (int q16 = 0; q16 < 4; q16++) {
                    uint2 v;
                    v.x = *(unsigned*)&hp[2 * q16];
                    v.y = *(unsigned*)&hp[2 * q16 + 1];
                    *(uint2*)&g_nproj_h[(size_t)n * 64 + q16 * 16 + tg * 4] = v;
                }
            }
        }
        return;
    }

    int pb = bx - npb;
    if (pb < B) {
        // ================= FiLM, MLP-16 =================
        __shared__ float part[2 * EDGE_DIM];
        int b = pb;
        int j = tid & 127;
        int h = tid >> 7;
        const float* crow = cond + (size_t)b * COND_DIM + h * 256;
        const float* wcol = Wc + (size_t)h * 256 * (2 * EDGE_DIM) + j;
        float accs[16];
        #pragma unroll
        for (int u = 0; u < 16; u++) accs[u] = 0.f;
        for (int k0 = 0; k0 < 256; k0 += 16) {
            #pragma unroll
            for (int u = 0; u < 16; u++)
                accs[u] = fmaf(crow[k0 + u],
                               wcol[(size_t)(k0 + u) * (2 * EDGE_DIM)],
                               accs[u]);
        }
        #pragma unroll
        for (int s = 8; s > 0; s >>= 1)
            #pragma unroll
            for (int u = 0; u < 8; u++)
                if (u < s) accs[u] += accs[u + s];
        float acc = accs[0];
        if (h == 1) part[j] = acc;
        __syncthreads();
        if (h == 0) {
            acc += part[j] + bc[j];
            if (j < EDGE_DIM) acc += 1.0f;
            g_gamma_beta[b * (2 * EDGE_DIM) + j] = acc;
        }
    } else if (pb < B + WCOMB_BLOCKS) {
        int idx = (pb - B) * 256 + tid;
        if (idx < KPAD * EDGE_DIM) {
            int k = idx >> 6, c = idx & 63;
            float v = 0.f;
            if (k < EDGE_DIM) {
                v = Wx[k * EDGE_DIM + c];               // natural order
            } else if (k < KTOT) {
                int gk = k - EDGE_DIM;
                #pragma unroll
                for (int m = 0; m < GEO_OUT; m++)
                    v += Wg[gk * GEO_OUT + m] * Wx[(EDGE_DIM + m) * EDGE_DIM + c];
            }
            g_wcomb_h[idx] = __float2half_rn(v);
        }
        if (pb == B && tid < EDGE_DIM) {
            int c = tid;
            float v = 0.f;
            #pragma unroll
            for (int m = 0; m < GEO_OUT; m++)
                v += bg[m] * Wx[(EDGE_DIM + m) * EDGE_DIM + c];
            g_cbias[c] = v;
        }
    } else {
        // dtype probe: values < 2^17; nonzero high word => int32 packing
        __shared__ int bad[2];
        if (tid == 0) { bad[0] = 0; bad[1] = 0; }
        __syncthreads();
        const unsigned long long* p64 = (const unsigned long long*)ei;
        const unsigned long long* b64 = (const unsigned long long*)bids;
        const int samples = 2048;
        long long st_e = (long long)E / samples; if (st_e < 1) st_e = 1;
        for (int i = tid; i < samples; i += blockDim.x) {
            long long idx = (long long)i * st_e;
            if (idx >= E) break;
            if (p64[idx] >> 32) bad[0] = 1;
        }
        long long n_b = E / 2;
        long long st_b = n_b / samples; if (st_b < 1) st_b = 1;
        for (int i = tid; i < samples; i += blockDim.x) {
            long long idx = (long long)i * st_b;
            if (idx >= n_b) break;
            if (b64[idx] >> 32) bad[1] = 1;
        }
        __syncthreads();
        if (tid == 0) { g_ei_is64 = !bad[0]; g_bid_is64 = !bad[1]; }
    }
}

// ---------------------------------------------------------------------------
// Edge kernel: cp.async pipeline, LDS.64 A-frags (paired-k layout),
// beta' fold, sector-aligned STG.64 epilogue, bids prefetched at tile top.
// ---------------------------------------------------------------------------
__global__ __launch_bounds__(256, 2) void edge_kernel(const void* __restrict__ ei,
                                                      const void* __restrict__ bids,
                                                      const float* __restrict__ e_geo,
                                                      float* __restrict__ out,
                                                      int E, int ntiles) {
    extern __shared__ __align__(16) char sm[];
    char*   RAW  = sm + SM_RAW_OFF;
    char*   IDX  = sm + SM_IDX_OFF;
    __half* Wt   = (__half*)(sm + SM_W_OFF);
    __half* GBs  = (__half*)(sm + SM_GB_OFF);

    const int tid = threadIdx.x;
    const int lane = tid & 31;
    const int wid = tid >> 5;
    const int ei64 = g_ei_is64;
    const int bid64 = g_bid_is64;
    const int esz = ei64 ? 8 : 4;

    for (int i = tid; i < KTOT * EDGE_DIM; i += 256) {
        int k = i / 64, n = i & 63;
        Wt[n * WT_STRIDE + k] = g_wcomb_h[k * 64 + n];
    }
    // gamma as-is; beta' = beta + cbias*gamma
    for (int i = tid; i < 64 * 2 * EDGE_DIM; i += 256) {
        int b = i >> 7, c = i & 127;
        float v = g_gamma_beta[i];
        if (c >= 64)
            v += g_cbias[c - 64] * g_gamma_beta[b * 128 + (c - 64)];
        GBs[b * GB_STRIDE + c] = __float2half_rn(v);
    }
    __syncthreads();

    const int gid = lane >> 2;
    const int tg = lane & 3;

    unsigned bfr[8][4];
    unsigned b8[8];
    #pragma unroll
    for (int nj = 0; nj < 8; nj++) {
        const __half* wr = Wt + (nj * 8 + gid) * WT_STRIDE;
        #pragma unroll
        for (int ks = 0; ks < 2; ks++) {
            bfr[nj][ks * 2 + 0] = *(const unsigned*)&wr[ks * 16 + tg * 2];
            bfr[nj][ks * 2 + 1] = *(const unsigned*)&wr[ks * 16 + 8 + tg * 2];
        }
        b8[nj] = *(const unsigned*)&wr[64 + tg * 2];
    }

    const int rowS = wid * 16 + gid;

    auto copy_idx = [&](int tile, int buf) {
        int e0 = tile * EDGE_TILE;
        int nch = 8 * esz;
        int epc = 16 / esz;
        char* dst = IDX + buf * SM_IDX_B;
        if (tid < nch) {
            if (e0 + tid * epc < E)
                cpa16(dst + tid * 16, (const char*)ei + (size_t)e0 * esz + tid * 16);
        } else if (tid >= 128 && tid - 128 < nch) {
            int t = tid - 128;
            if (e0 + t * epc < E)
                cpa16(dst + nch * 16 + t * 16,
                      (const char*)ei + ((size_t)E + e0) * esz + t * 16);
        }
    };
    auto gather_raw = [&](int tile, int rbuf, int ibuf) {
        int e0 = tile * EDGE_TILE;
        char* rb = RAW + rbuf * RAW_BUF_B;
        const char* idxb = IDX + ibuf * SM_IDX_B;
        #pragma unroll
        for (int j = 0; j < 8; j++) {
            int g = j * 256 + tid;
            int row = g >> 3, c = g & 7;
            int e = e0 + (row & 127);
            int idx = 0;
            if (e < E)
                idx = ei64 ? (int)((const long long*)idxb)[row]
                           : ((const int*)idxb)[row];
            cpa16(rb + row * 128 + ((c ^ (row & 7)) * 16),
                  (const char*)g_nproj_h + (size_t)idx * 128 + c * 16);
        }
    };

    int tile = blockIdx.x;
    if (tile >= ntiles) return;
    const int stride = gridDim.x;

    copy_idx(tile, 0);
    CP_COMMIT();
    CP_WAIT0();
    __syncthreads();
    gather_raw(tile, 0, 0);
    { int t1 = tile + stride; if (t1 < ntiles) copy_idx(t1, 1); }
    CP_COMMIT();

    for (int i = 0; tile < ntiles; tile += stride, i++) {
        CP_WAIT0();
        __syncthreads();

        int e0 = tile * EDGE_TILE;

        // prefetch bids + geo for this tile's epilogue rows (hide L2 latency)
        int e1 = e0 + wid * 16 + gid;
        int e2 = e1 + 8;
        int bb0i = 0, bb1i = 0;
        if (e1 < E) bb0i = bid64 ? (int)((const long long*)bids)[e1]
                                 : ((const int*)bids)[e1];
        if (e2 < E) bb1i = bid64 ? (int)((const long long*)bids)[e2]
                                 : ((const int*)bids)[e2];
        float2 gv0 = make_float2(0.f, 0.f), gv1 = make_float2(0.f, 0.f);
        if (e1 < E) gv0 = *(const float2*)&e_geo[(size_t)e1 * GEO_DIM + tg * 2];
        if (e2 < E) gv1 = *(const float2*)&e_geo[(size_t)e2 * GEO_DIM + tg * 2];

        {   // issue next tile's gather + next-next idx prefetch
            int t1 = tile + stride;
            int t2 = tile + 2 * stride;
            if (t1 < ntiles) gather_raw(t1, (i + 1) & 1, (i + 1) & 1);
            if (t2 < ntiles) copy_idx(t2, i & 1);
            CP_COMMIT();
        }

        const char* rbase = RAW + (i & 1) * RAW_BUF_B;

        float acc[8][4];
        #pragma unroll
        for (int nj = 0; nj < 8; nj++)
            #pragma unroll
            for (int q = 0; q < 4; q++) acc[nj][q] = 0.f;

        #pragma unroll
        for (int ks = 0; ks < 4; ks++) {
            int q = ks * 4 + tg;
            int off = (((q >> 1) ^ gid) * 16) + ((q & 1) * 8);
            const char* sp = rbase + rowS * 128 + off;
            uint2 s0 = *(const uint2*)(sp);
            uint2 s1 = *(const uint2*)(sp + 8 * 128);
            uint2 d0 = *(const uint2*)(sp + 128 * 128);
            uint2 d1 = *(const uint2*)(sp + 136 * 128);
            __half2 p0 = __hmul2(*(__half2*)&s0.x, *(__half2*)&d0.x);
            __half2 p2 = __hmul2(*(__half2*)&s0.y, *(__half2*)&d0.y);
            __half2 p1 = __hmul2(*(__half2*)&s1.x, *(__half2*)&d1.x);
            __half2 p3 = __hmul2(*(__half2*)&s1.y, *(__half2*)&d1.y);
            unsigned a0 = *(unsigned*)&p0;
            unsigned a1 = *(unsigned*)&p1;
            unsigned a2 = *(unsigned*)&p2;
            unsigned a3 = *(unsigned*)&p3;
            #pragma unroll
            for (int nj = 0; nj < 8; nj++) {
                unsigned bb0, bb1;
                if (ks < 2) {
                    bb0 = bfr[nj][ks * 2];
                    bb1 = bfr[nj][ks * 2 + 1];
                } else {
                    const __half* wr = Wt + (nj * 8 + gid) * WT_STRIDE + ks * 16;
                    bb0 = *(const unsigned*)&wr[tg * 2];
                    bb1 = *(const unsigned*)&wr[8 + tg * 2];
                }
                asm volatile(
                    "mma.sync.aligned.m16n8k16.row.col.f32.f16.f16.f32 "
                    "{%0,%1,%2,%3}, {%4,%5,%6,%7}, {%8,%9}, {%0,%1,%2,%3};\n"
                    : "+f"(acc[nj][0]), "+f"(acc[nj][1]),
                      "+f"(acc[nj][2]), "+f"(acc[nj][3])
                    : "r"(a0), "r"(a1), "r"(a2), "r"(a3),
                      "r"(bb0), "r"(bb1));
            }
        }
        {
            __half2 h0 = __floats2half2_rn(gv0.x, gv0.y);
            __half2 h1 = __floats2half2_rn(gv1.x, gv1.y);
            unsigned ag0 = *(unsigned*)&h0;
            unsigned ag1 = *(unsigned*)&h1;
            #pragma unroll
            for (int nj = 0; nj < 8; nj++) {
                asm volatile(
                    "mma.sync.aligned.m16n8k8.row.col.f32.f16.f16.f32 "
                    "{%0,%1,%2,%3}, {%4,%5}, {%6}, {%0,%1,%2,%3};\n"
                    : "+f"(acc[nj][0]), "+f"(acc[nj][1]),
                      "+f"(acc[nj][2]), "+f"(acc[nj][3])
                    : "r"(ag0), "r"(ag1), "r"(b8[nj]));
            }
        }

        // epilogue: FiLM (gamma, beta') + relu, sector-aligned float2 stores
        #pragma unroll
        for (int h = 0; h < 2; h++) {
            int e = (h == 0) ? e1 : e2;
            if (e < E) {
                int bb = (h == 0) ? bb0i : bb1i;
                const __half* gb = GBs + bb * GB_STRIDE;
                #pragma unroll
                for (int nj = 0; nj < 8; nj++) {
                    int col = nj * 8 + tg * 2;
                    float2 ga = __half22float2(*(const __half2*)&gb[col]);
                    float2 be = __half22float2(*(const __half2*)&gb[64 + col]);
                    float2 o;
                    o.x = fmaxf(fmaf(acc[nj][h * 2 + 0], ga.x, be.x), 0.f);
                    o.y = fmaxf(fmaf(acc[nj][h * 2 + 1], ga.y, be.y), 0.f);
                    *(float2*)&out[(size_t)e * 64 + col] = o;
                }
            }
        }
    }
}

// ---------------------------------------------------------------------------
extern "C" void kernel_launch(void* const* d_in, const int* in_sizes, int n_in,
                              void* d_out, int out_size) {
    const float* nf   = (const float*)d_in[0];
    const void*  ei   = d_in[1];
    const float* eg   = (const float*)d_in[2];
    const float* cond = (const float*)d_in[3];
    const void*  bids = d_in[4];
    const float* Wn   = (const float*)d_in[5];
    const float* bn   = (const float*)d_in[6];
    const float* Wg   = (const float*)d_in[7];
    const float* bg   = (const float*)d_in[8];
    const float* Wc   = (const float*)d_in[9];
    const float* bc   = (const float*)d_in[10];
    const float* Wx   = (const float*)d_in[11];
    float* out = (float*)d_out;

    int N = in_sizes[0] / NODE_DIM;
    int E = in_sizes[2] / GEO_DIM;
    int B = in_sizes[3] / COND_DIM;
    int ntiles = (E + EDGE_TILE - 1) / EDGE_TILE;
    int npb = (N + 127) / 128;

    static int smem_set = 0;
    if (!smem_set) {
        cudaFuncSetAttribute(edge_kernel,
                             cudaFuncAttributeMaxDynamicSharedMemorySize,
                             SM_TOTAL);
        smem_set = 1;
    }

    fused_kernel<<<npb + B + WCOMB_BLOCKS + 1, 256>>>(nf, Wn, bn, cond, Wc, bc,
                                                      Wg, bg, Wx, ei, bids,
                                                      N, B, E, npb);
    int grid = 296;
    if (grid > ntiles) grid = ntiles;
    edge_kernel<<<grid, 256, SM_TOTAL>>>(ei, bids, eg, out, E, ntiles);
}

// round 17
// speedup vs baseline: 1.2261x; 1.0740x over previous
#include <cuda_runtime.h>
#include <cuda_fp16.h>
#include <stdint.h>

// ---------------------------------------------------------------------------
// EdgeFeat, Round 16: prep blocks scheduled FIRST in fused grid (overlap with
// nproj instead of serial tail); gamma/beta' packed-pair table (LDS.64);
// bids/geo prefetch hoisted above CP_WAIT0. Edge core = 118.8us winner.
// ---------------------------------------------------------------------------

#define NODE_DIM 64
#define EDGE_DIM 64
#define GEO_DIM  8
#define GEO_OUT  32
#define COND_DIM 512
#define KTOT     72
#define KPAD     80
#define MAX_NODES  100000
#define MAX_EDGES  800000
#define MAX_GRAPHS 64

#define EDGE_TILE 128
#define WT_STRIDE 88           // halfs
#define GBP_STRIDE 33          // uint2 pairs per graph (32 data + 1 pad)

// edge smem layout (bytes)
#define RAW_BUF_B  (256 * 128)                            // 32768
#define SM_RAW_OFF 0
#define SM_IDX_OFF (2 * RAW_BUF_B)                        // 65536
#define SM_IDX_B   2048
#define SM_W_OFF   (SM_IDX_OFF + 2 * SM_IDX_B)            // 69632
#define SM_W_B     (64 * WT_STRIDE * 2)                   // 11264
#define SM_GB_OFF  (SM_W_OFF + SM_W_B)                    // 80896
#define SM_GB_B    (64 * GBP_STRIDE * 8)                  // 16896
#define SM_TOTAL   (SM_GB_OFF + SM_GB_B)                  // 97792

__device__ __half g_nproj_h[MAX_NODES * NODE_DIM];   // paired-k permuted cols
__device__ float  g_gamma_beta[MAX_GRAPHS * 2 * EDGE_DIM];
__device__ __half g_wcomb_h[KPAD * EDGE_DIM];        // [k][n], natural order
__device__ float  g_cbias[EDGE_DIM];
__device__ int    g_ei_is64;
__device__ int    g_bid_is64;

struct __align__(8) Half4 { __half2 lo, hi; };

__device__ __forceinline__ void cpa16(void* smp, const void* g) {
    unsigned sa = (unsigned)__cvta_generic_to_shared(smp);
    asm volatile("cp.async.cg.shared.global [%0], [%1], 16;" :: "r"(sa), "l"(g) : "memory");
}
#define CP_COMMIT() asm volatile("cp.async.commit_group;" ::: "memory")
#define CP_WAIT0()  asm volatile("cp.async.wait_group 0;" ::: "memory")

#define WCOMB_BLOCKS 20
#define PREP_B (64 + WCOMB_BLOCKS + 1)   // FiLM(64) + wcomb(20) + detect(1)
#define NW_STRIDE 72   // halfs

// ---------------------------------------------------------------------------
// Fused kernel: blocks [0,PREP_B) = FiLM / Wcomb+cbias / detect (run FIRST,
// overlapping nproj); blocks [PREP_B, PREP_B+npb) = nproj fp16-MMA tiles.
// ---------------------------------------------------------------------------
__global__ __launch_bounds__(256) void fused_kernel(const float* __restrict__ nf,
                                                    const float* __restrict__ Wn,
                                                    const float* __restrict__ bn,
                                                    const float* __restrict__ cond,
                                                    const float* __restrict__ Wc,
                                                    const float* __restrict__ bc,
                                                    const float* __restrict__ Wg,
                                                    const float* __restrict__ bg,
                                                    const float* __restrict__ Wx,
                                                    const void* __restrict__ ei,
                                                    const void* __restrict__ bids,
                                                    int N, int B, int E, int npb) {
    int bx = blockIdx.x;
    int tid = threadIdx.x;

    if (bx >= PREP_B) {
        // ================= nproj tile (fp16 MMA) =================
        __shared__ __align__(16) __half As[128 * 64];
        __shared__ __align__(16) __half Ws[64 * NW_STRIDE];
        int lane = tid & 31;
        int wid = tid >> 5;
        int n0 = (bx - PREP_B) * 128;

        for (int i = tid; i < 64 * 64; i += 256) {
            int k = i >> 6, n = i & 63;
            Ws[n * NW_STRIDE + k] = __float2half_rn(Wn[k * 64 + n]);
        }
        {
            int row = tid >> 1, h = tid & 1;
            int n = n0 + row;
            #pragma unroll
            for (int j = 0; j < 4; j++) {
                int c = h * 4 + j;
                int base = row * 64 + ((c ^ (row & 7)) * 8);
                if (n < N) {
                    float4 a = *(const float4*)&nf[(size_t)n * 64 + c * 8];
                    float4 b = *(const float4*)&nf[(size_t)n * 64 + c * 8 + 4];
                    Half4 hv, hv2;
                    hv.lo  = __floats2half2_rn(a.x, a.y);
                    hv.hi  = __floats2half2_rn(a.z, a.w);
                    hv2.lo = __floats2half2_rn(b.x, b.y);
                    hv2.hi = __floats2half2_rn(b.z, b.w);
                    *(Half4*)&As[base]     = hv;
                    *(Half4*)&As[base + 4] = hv2;
                } else {
                    Half4 hv;
                    hv.lo = __float2half2_rn(0.f);
                    hv.hi = __float2half2_rn(0.f);
                    *(Half4*)&As[base]     = hv;
                    *(Half4*)&As[base + 4] = hv;
                }
            }
        }
        __syncthreads();

        int gid = lane >> 2;
        int tg = lane & 3;
        float2 bnj[8];
        #pragma unroll
        for (int nj = 0; nj < 8; nj++)
            bnj[nj] = *(const float2*)&bn[nj * 8 + tg * 2];

        float acc[8][4];
        #pragma unroll
        for (int nj = 0; nj < 8; nj++)
            #pragma unroll
            for (int q = 0; q < 4; q++) acc[nj][q] = 0.f;

        const char* rbase = (const char*)As;
        const int roff  = (wid * 16 + gid) * 128 + tg * 4;
        const int roff8 = roff + 8 * 128;

        #pragma unroll
        for (int ks = 0; ks < 4; ks++) {
            int co0 = ((2 * ks) ^ gid) * 16;
            int co1 = ((2 * ks + 1) ^ gid) * 16;
            unsigned a0 = *(const unsigned*)(rbase + roff  + co0);
            unsigned a1 = *(const unsigned*)(rbase + roff8 + co0);
            unsigned a2 = *(const unsigned*)(rbase + roff  + co1);
            unsigned a3 = *(const unsigned*)(rbase + roff8 + co1);
            #pragma unroll
            for (int nj = 0; nj < 8; nj++) {
                const __half* wr = Ws + (nj * 8 + gid) * NW_STRIDE + ks * 16;
                unsigned bb0 = *(const unsigned*)&wr[tg * 2];
                unsigned bb1 = *(const unsigned*)&wr[8 + tg * 2];
                asm volatile(
                    "mma.sync.aligned.m16n8k16.row.col.f32.f16.f16.f32 "
                    "{%0,%1,%2,%3}, {%4,%5,%6,%7}, {%8,%9}, {%0,%1,%2,%3};\n"
                    : "+f"(acc[nj][0]), "+f"(acc[nj][1]),
                      "+f"(acc[nj][2]), "+f"(acc[nj][3])
                    : "r"(a0), "r"(a1), "r"(a2), "r"(a3), "r"(bb0), "r"(bb1));
            }
        }

        // paired-k permuted store
        #pragma unroll
        for (int h = 0; h < 2; h++) {
            int n = n0 + wid * 16 + gid + h * 8;
            if (n < N) {
                __half2 hp[8];
                #pragma unroll
                for (int nj = 0; nj < 8; nj++)
                    hp[nj] = __floats2half2_rn(acc[nj][h * 2] + bnj[nj].x,
                                               acc[nj][h * 2 + 1] + bnj[nj].y);
                #pragma unroll
                for (int q16 = 0; q16 < 4; q16++) {
                    uint2 v;
                    v.x = *(unsigned*)&hp[2 * q16];
                    v.y = *(unsigned*)&hp[2 * q16 + 1];
                    *(uint2*)&g_nproj_h[(size_t)n * 64 + q16 * 16 + tg * 4] = v;
                }
            }
        }
        return;
    }

    if (bx < B) {
        // ================= FiLM, MLP-16 =================
        __shared__ float part[2 * EDGE_DIM];
        int b = bx;
        int j = tid & 127;
        int h = tid >> 7;
        const float* crow = cond + (size_t)b * COND_DIM + h * 256;
        const float* wcol = Wc + (size_t)h * 256 * (2 * EDGE_DIM) + j;
        float accs[16];
        #pragma unroll
        for (int u = 0; u < 16; u++) accs[u] = 0.f;
        for (int k0 = 0; k0 < 256; k0 += 16) {
            #pragma unroll
            for (int u = 0; u < 16; u++)
                accs[u] = fmaf(crow[k0 + u],
                               wcol[(size_t)(k0 + u) * (2 * EDGE_DIM)],
                               accs[u]);
        }
        #pragma unroll
        for (int s = 8; s > 0; s >>= 1)
            #pragma unroll
            for (int u = 0; u < 8; u++)
                if (u < s) accs[u] += accs[u + s];
        float acc = accs[0];
        if (h == 1) part[j] = acc;
        __syncthreads();
        if (h == 0) {
            acc += part[j] + bc[j];
            if (j < EDGE_DIM) acc += 1.0f;
            g_gamma_beta[b * (2 * EDGE_DIM) + j] = acc;
        }
    } else if (bx < B + WCOMB_BLOCKS) {
        int idx = (bx - B) * 256 + tid;
        if (idx < KPAD * EDGE_DIM) {
            int k = idx >> 6, c = idx & 63;
            float v = 0.f;
            if (k < EDGE_DIM) {
                v = Wx[k * EDGE_DIM + c];               // natural order
            } else if (k < KTOT) {
                int gk = k - EDGE_DIM;
                #pragma unroll
                for (int m = 0; m < GEO_OUT; m++)
                    v += Wg[gk * GEO_OUT + m] * Wx[(EDGE_DIM + m) * EDGE_DIM + c];
            }
            g_wcomb_h[idx] = __float2half_rn(v);
        }
        if (bx == B && tid < EDGE_DIM) {
            int c = tid;
            float v = 0.f;
            #pragma unroll
            for (int m = 0; m < GEO_OUT; m++)
                v += bg[m] * Wx[(EDGE_DIM + m) * EDGE_DIM + c];
            g_cbias[c] = v;
        }
    } else {
        // dtype probe: values < 2^17; nonzero high word => int32 packing
        __shared__ int bad[2];
        if (tid == 0) { bad[0] = 0; bad[1] = 0; }
        __syncthreads();
        const unsigned long long* p64 = (const unsigned long long*)ei;
        const unsigned long long* b64 = (const unsigned long long*)bids;
        const int samples = 2048;
        long long st_e = (long long)E / samples; if (st_e < 1) st_e = 1;
        for (int i = tid; i < samples; i += blockDim.x) {
            long long idx = (long long)i * st_e;
            if (idx >= E) break;
            if (p64[idx] >> 32) bad[0] = 1;
        }
        long long n_b = E / 2;
        long long st_b = n_b / samples; if (st_b < 1) st_b = 1;
        for (int i = tid; i < samples; i += blockDim.x) {
            long long idx = (long long)i * st_b;
            if (idx >= n_b) break;
            if (b64[idx] >> 32) bad[1] = 1;
        }
        __syncthreads();
        if (tid == 0) { g_ei_is64 = !bad[0]; g_bid_is64 = !bad[1]; }
    }
}

// ---------------------------------------------------------------------------
// Edge kernel: cp.async pipeline, LDS.64 A-frags, packed gamma/beta' pairs,
// sector-aligned STG.64 epilogue, bids/geo prefetch above CP_WAIT0.
// ---------------------------------------------------------------------------
__global__ __launch_bounds__(256, 2) void edge_kernel(const void* __restrict__ ei,
                                                      const void* __restrict__ bids,
                                                      const float* __restrict__ e_geo,
                                                      float* __restrict__ out,
                                                      int E, int ntiles) {
    extern __shared__ __align__(16) char sm[];
    char*   RAW  = sm + SM_RAW_OFF;
    char*   IDX  = sm + SM_IDX_OFF;
    __half* Wt   = (__half*)(sm + SM_W_OFF);
    uint2*  GBP  = (uint2*)(sm + SM_GB_OFF);

    const int tid = threadIdx.x;
    const int lane = tid & 31;
    const int wid = tid >> 5;
    const int ei64 = g_ei_is64;
    const int bid64 = g_bid_is64;
    const int esz = ei64 ? 8 : 4;

    for (int i = tid; i < KTOT * EDGE_DIM; i += 256) {
        int k = i / 64, n = i & 63;
        Wt[n * WT_STRIDE + k] = g_wcomb_h[k * 64 + n];
    }
    // packed pairs: GBP[b][p] = {gamma2(2p,2p+1), beta'2(2p,2p+1)}
    for (int i = tid; i < 64 * 32; i += 256) {
        int b = i >> 5, p = i & 31;
        float g0 = g_gamma_beta[b * 128 + 2 * p];
        float g1 = g_gamma_beta[b * 128 + 2 * p + 1];
        float be0 = g_gamma_beta[b * 128 + 64 + 2 * p]     + g_cbias[2 * p] * g0;
        float be1 = g_gamma_beta[b * 128 + 64 + 2 * p + 1] + g_cbias[2 * p + 1] * g1;
        __half2 hg = __floats2half2_rn(g0, g1);
        __half2 hb = __floats2half2_rn(be0, be1);
        uint2 v;
        v.x = *(unsigned*)&hg;
        v.y = *(unsigned*)&hb;
        GBP[b * GBP_STRIDE + p] = v;
    }
    __syncthreads();

    const int gid = lane >> 2;
    const int tg = lane & 3;

    unsigned bfr[8][4];
    unsigned b8[8];
    #pragma unroll
    for (int nj = 0; nj < 8; nj++) {
        const __half* wr = Wt + (nj * 8 + gid) * WT_STRIDE;
        #pragma unroll
        for (int ks = 0; ks < 2; ks++) {
            bfr[nj][ks * 2 + 0] = *(const unsigned*)&wr[ks * 16 + tg * 2];
            bfr[nj][ks * 2 + 1] = *(const unsigned*)&wr[ks * 16 + 8 + tg * 2];
        }
        b8[nj] = *(const unsigned*)&wr[64 + tg * 2];
    }

    const int rowS = wid * 16 + gid;

    auto copy_idx = [&](int tile, int buf) {
        int e0 = tile * EDGE_TILE;
        int nch = 8 * esz;
        int epc = 16 / esz;
        char* dst = IDX + buf * SM_IDX_B;
        if (tid < nch) {
            if (e0 + tid * epc < E)
                cpa16(dst + tid * 16, (const char*)ei + (size_t)e0 * esz + tid * 16);
        } else if (tid >= 128 && tid - 128 < nch) {
            int t = tid - 128;
            if (e0 + t * epc < E)
                cpa16(dst + nch * 16 + t * 16,
                      (const char*)ei + ((size_t)E + e0) * esz + t * 16);
        }
    };
    auto gather_raw = [&](int tile, int rbuf, int ibuf) {
        int e0 = tile * EDGE_TILE;
        char* rb = RAW + rbuf * RAW_BUF_B;
        const char* idxb = IDX + ibuf * SM_IDX_B;
        #pragma unroll
        for (int j = 0; j < 8; j++) {
            int g = j * 256 + tid;
            int row = g >> 3, c = g & 7;
            int e = e0 + (row & 127);
            int idx = 0;
            if (e < E)
                idx = ei64 ? (int)((const long long*)idxb)[row]
                           : ((const int*)idxb)[row];
            cpa16(rb + row * 128 + ((c ^ (row & 7)) * 16),
                  (const char*)g_nproj_h + (size_t)idx * 128 + c * 16);
        }
    };

    int tile = blockIdx.x;
    if (tile >= ntiles) return;
    const int stride = gridDim.x;

    copy_idx(tile, 0);
    CP_COMMIT();
    CP_WAIT0();
    __syncthreads();
    gather_raw(tile, 0, 0);
    { int t1 = tile + stride; if (t1 < ntiles) copy_idx(t1, 1); }
    CP_COMMIT();

    for (int i = 0; tile < ntiles; tile += stride, i++) {
        int e0 = tile * EDGE_TILE;

        // prefetch bids + geo (independent of RAW) before the async wait
        int e1 = e0 + wid * 16 + gid;
        int e2 = e1 + 8;
        int bb0i = 0, bb1i = 0;
        if (e1 < E) bb0i = bid64 ? (int)((const long long*)bids)[e1]
                                 : ((const int*)bids)[e1];
        if (e2 < E) bb1i = bid64 ? (int)((const long long*)bids)[e2]
                                 : ((const int*)bids)[e2];
        float2 gv0 = make_float2(0.f, 0.f), gv1 = make_float2(0.f, 0.f);
        if (e1 < E) gv0 = *(const float2*)&e_geo[(size_t)e1 * GEO_DIM + tg * 2];
        if (e2 < E) gv1 = *(const float2*)&e_geo[(size_t)e2 * GEO_DIM + tg * 2];

        CP_WAIT0();
        __syncthreads();

        {   // issue next tile's gather + next-next idx prefetch
            int t1 = tile + stride;
            int t2 = tile + 2 * stride;
            if (t1 < ntiles) gather_raw(t1, (i + 1) & 1, (i + 1) & 1);
            if (t2 < ntiles) copy_idx(t2, i & 1);
            CP_COMMIT();
        }

        const char* rbase = RAW + (i & 1) * RAW_BUF_B;

        float acc[8][4];
        #pragma unroll
        for (int nj = 0; nj < 8; nj++)
            #pragma unroll
            for (int q = 0; q < 4; q++) acc[nj][q] = 0.f;

        #pragma unroll
        for (int ks = 0; ks < 4; ks++) {
            int q = ks * 4 + tg;
            int off = (((q >> 1) ^ gid) * 16) + ((q & 1) * 8);
            const char* sp = rbase + rowS * 128 + off;
            uint2 s0 = *(const uint2*)(sp);
            uint2 s1 = *(const uint2*)(sp + 8 * 128);
            uint2 d0 = *(const uint2*)(sp + 128 * 128);
            uint2 d1 = *(const uint2*)(sp + 136 * 128);
            __half2 p0 = __hmul2(*(__half2*)&s0.x, *(__half2*)&d0.x);
            __half2 p2 = __hmul2(*(__half2*)&s0.y, *(__half2*)&d0.y);
            __half2 p1 = __hmul2(*(__half2*)&s1.x, *(__half2*)&d1.x);
            __half2 p3 = __hmul2(*(__half2*)&s1.y, *(__half2*)&d1.y);
            unsigned a0 = *(unsigned*)&p0;
            unsigned a1 = *(unsigned*)&p1;
            unsigned a2 = *(unsigned*)&p2;
            unsigned a3 = *(unsigned*)&p3;
            #pragma unroll
            for (int nj = 0; nj < 8; nj++) {
                unsigned bb0, bb1;
                if (ks < 2) {
                    bb0 = bfr[nj][ks * 2];
                    bb1 = bfr[nj][ks * 2 + 1];
                } else {
                    const __half* wr = Wt + (nj * 8 + gid) * WT_STRIDE + ks * 16;
                    bb0 = *(const unsigned*)&wr[tg * 2];
                    bb1 = *(const unsigned*)&wr[8 + tg * 2];
                }
                asm volatile(
                    "mma.sync.aligned.m16n8k16.row.col.f32.f16.f16.f32 "
                    "{%0,%1,%2,%3}, {%4,%5,%6,%7}, {%8,%9}, {%0,%1,%2,%3};\n"
                    : "+f"(acc[nj][0]), "+f"(acc[nj][1]),
                      "+f"(acc[nj][2]), "+f"(acc[nj][3])
                    : "r"(a0), "r"(a1), "r"(a2), "r"(a3),
                      "r"(bb0), "r"(bb1));
            }
        }
        {
            __half2 h0 = __floats2half2_rn(gv0.x, gv0.y);
            __half2 h1 = __floats2half2_rn(gv1.x, gv1.y);
            unsigned ag0 = *(unsigned*)&h0;
            unsigned ag1 = *(unsigned*)&h1;
            #pragma unroll
            for (int nj = 0; nj < 8; nj++) {
                asm volatile(
                    "mma.sync.aligned.m16n8k8.row.col.f32.f16.f16.f32 "
                    "{%0,%1,%2,%3}, {%4,%5}, {%6}, {%0,%1,%2,%3};\n"
                    : "+f"(acc[nj][0]), "+f"(acc[nj][1]),
                      "+f"(acc[nj][2]), "+f"(acc[nj][3])
                    : "r"(ag0), "r"(ag1), "r"(b8[nj]));
            }
        }

        // epilogue: packed gamma/beta' pairs + relu, sector-aligned stores
        #pragma unroll
        for (int h = 0; h < 2; h++) {
            int e = (h == 0) ? e1 : e2;
            if (e < E) {
                int bb = (h == 0) ? bb0i : bb1i;
                const uint2* gp = GBP + bb * GBP_STRIDE + tg;
                #pragma unroll
                for (int nj = 0; nj < 8; nj++) {
                    uint2 v = gp[nj * 4];
                    float2 ga = __half22float2(*(__half2*)&v.x);
                    float2 be = __half22float2(*(__half2*)&v.y);
                    float2 o;
                    o.x = fmaxf(fmaf(acc[nj][h * 2 + 0], ga.x, be.x), 0.f);
                    o.y = fmaxf(fmaf(acc[nj][h * 2 + 1], ga.y, be.y), 0.f);
                    *(float2*)&out[(size_t)e * 64 + nj * 8 + tg * 2] = o;
                }
            }
        }
    }
}

// ---------------------------------------------------------------------------
extern "C" void kernel_launch(void* const* d_in, const int* in_sizes, int n_in,
                              void* d_out, int out_size) {
    const float* nf   = (const float*)d_in[0];
    const void*  ei   = d_in[1];
    const float* eg   = (const float*)d_in[2];
    const float* cond = (const float*)d_in[3];
    const void*  bids = d_in[4];
    const float* Wn   = (const float*)d_in[5];
    const float* bn   = (const float*)d_in[6];
    const float* Wg   = (const float*)d_in[7];
    const float* bg   = (const float*)d_in[8];
    const float* Wc   = (const float*)d_in[9];
    const float* bc   = (const float*)d_in[10];
    const float* Wx   = (const float*)d_in[11];
    float* out = (float*)d_out;

    int N = in_sizes[0] / NODE_DIM;
    int E = in_sizes[2] / GEO_DIM;
    int B = in_sizes[3] / COND_DIM;
    int ntiles = (E + EDGE_TILE - 1) / EDGE_TILE;
    int npb = (N + 127) / 128;

    static int smem_set = 0;
    if (!smem_set) {
        cudaFuncSetAttribute(edge_kernel,
                             cudaFuncAttributeMaxDynamicSharedMemorySize,
                             SM_TOTAL);
        smem_set = 1;
    }

    fused_kernel<<<PREP_B + npb, 256>>>(nf, Wn, bn, cond, Wc, bc,
                                        Wg, bg, Wx, ei, bids,
                                        N, B, E, npb);
    int grid = 296;
    if (grid > ntiles) grid = ntiles;
    edge_kernel<<<grid, 256, SM_TOTAL>>>(ei, bids, eg, out, E, ntiles);
}